// round 6
// baseline (speedup 1.0000x reference)
#include <cuda_runtime.h>
#include <cstdint>

// PointPillarsBEV R5 (resubmit — R5 bench was an infra failure, theory untested).
// R4 failure: PFN blocks (bids 0..1499) and expand blocks (1500..) never co-resided
// (CLC places contiguous bids -> wave 1 was pure PFN). Fix: stripe is_pfn=(bid&3)==3.
// Also: expand amortizes one uchar4 flag load over 4 channel stores (flag traffic /4).
// Pipeline: prep ; pfn(0) ; {expand(b-1)|pfn(b)} x3 striped ; expand(3).

#define BEV_W 512
#define NPILLARS 12000
#define NPTS 32
#define DIN 10
#define CCH 64
#define HW 262144                    // 512*512
#define PPB 8
#define NPFN (NPILLARS / PPB)        // 1500
#define NEXP 4096                    // expand chunks per batch (256 thr each)
#define STRIPED_GRID 6000            // 1500 pfn (bid&3==3) + 4500 expand slots

__device__ float g_acc[(size_t)4 * HW * CCH];          // 268MB staging (touched lines only)
__device__ unsigned char g_flag[4 * HW];               // 1MB

__device__ __forceinline__ uint64_t pack2(float lo, float hi) {
    uint64_t r; asm("mov.b64 %0, {%1, %2};" : "=l"(r) : "f"(lo), "f"(hi)); return r;
}
__device__ __forceinline__ void unpack2(uint64_t v, float& lo, float& hi) {
    asm("mov.b64 {%0, %1}, %2;" : "=f"(lo), "=f"(hi) : "l"(v));
}
__device__ __forceinline__ uint64_t fma2(uint64_t a, uint64_t b, uint64_t c) {
    uint64_t d; asm("fma.rn.f32x2 %0, %1, %2, %3;" : "=l"(d) : "l"(a), "l"(b), "l"(c)); return d;
}

// ---------------- prep: zero flags + zero touched acc cells ----------------
__global__ __launch_bounds__(256) void prep_kernel(const int* __restrict__ coords) {
    if (blockIdx.x < 256) {
        ((uint4*)g_flag)[blockIdx.x * 256 + threadIdx.x] = make_uint4(0, 0, 0, 0);
    } else {
        const int warp = threadIdx.x >> 5, lane = threadIdx.x & 31;
        const int pidx = (blockIdx.x - 256) * PPB + warp;      // [0, 48000)
        const int b = pidx / NPILLARS;
        const int y = __ldg(&coords[(size_t)pidx * 2 + 0]);
        const int x = __ldg(&coords[(size_t)pidx * 2 + 1]);
        const size_t base = ((size_t)(b * HW) + y * BEV_W + x) * CCH;
        ((float2*)(g_acc + base))[lane] = make_float2(0.f, 0.f);
    }
}

// ---------------- PFN + compact scatter: 1 warp per pillar ----------------
__device__ __forceinline__ void do_pfn(
    const float* __restrict__ pillars, const int* __restrict__ coords,
    const float* __restrict__ w, const float* __restrict__ bias,
    int batch, int pfnBlk)
{
    const int warp = threadIdx.x >> 5, lane = threadIdx.x & 31;
    const int p = pfnBlk * PPB + warp;

    __shared__ __align__(16) float s_pts[PPB][DIN][NPTS];   // dim-major

    const float2* src2 = (const float2*)(pillars +
        ((size_t)(batch * NPILLARS + p) * NPTS + lane) * DIN);
    float v[DIN];
    #pragma unroll
    for (int i = 0; i < 5; i++) { float2 t = src2[i]; v[2*i] = t.x; v[2*i+1] = t.y; }
    #pragma unroll
    for (int d = 0; d < DIN; d++) s_pts[warp][d][lane] = v[d];
    __syncwarp();

    uint64_t wA[DIN], wB[DIN];
    #pragma unroll
    for (int d = 0; d < DIN; d++) {
        float wa = w[d * CCH + lane], wb = w[d * CCH + lane + 32];
        wA[d] = pack2(wa, wa); wB[d] = pack2(wb, wb);
    }
    const float ba = bias[lane], bb = bias[lane + 32];
    const uint64_t biasA = pack2(ba, ba), biasB = pack2(bb, bb);

    float mA = 0.f, mB = 0.f;        // relu >= 0 -> 0-init exact
    #pragma unroll
    for (int q = 0; q < NPTS / 4; q++) {
        uint64_t x01[DIN], x23[DIN];
        #pragma unroll
        for (int d = 0; d < DIN; d++) {
            float4 t = *reinterpret_cast<const float4*>(&s_pts[warp][d][4 * q]);
            x01[d] = pack2(t.x, t.y); x23[d] = pack2(t.z, t.w);
        }
        uint64_t sA0 = biasA, sB0 = biasB, sA1 = biasA, sB1 = biasB;
        #pragma unroll
        for (int d = 0; d < DIN; d++) {
            sA0 = fma2(x01[d], wA[d], sA0); sB0 = fma2(x01[d], wB[d], sB0);
            sA1 = fma2(x23[d], wA[d], sA1); sB1 = fma2(x23[d], wB[d], sB1);
        }
        float lo, hi;
        unpack2(sA0, lo, hi); mA = fmaxf(mA, fmaxf(lo, hi));
        unpack2(sA1, lo, hi); mA = fmaxf(mA, fmaxf(lo, hi));
        unpack2(sB0, lo, hi); mB = fmaxf(mB, fmaxf(lo, hi));
        unpack2(sB1, lo, hi); mB = fmaxf(mB, fmaxf(lo, hi));
    }

    const int y = __ldg(&coords[(size_t)(batch * NPILLARS + p) * 2 + 0]);
    const int x = __ldg(&coords[(size_t)(batch * NPILLARS + p) * 2 + 1]);
    const int cell = batch * HW + y * BEV_W + x;
    if (lane == 0) g_flag[cell] = 1;
    float* a = g_acc + (size_t)cell * CCH;
    atomicAdd(a + lane, mA);                 // 256B contiguous REDG burst
    atomicAdd(a + lane + 32, mB);
}

// ---------------- expand one chunk: 1 flag load -> 4 channel stores ----------------
__device__ __forceinline__ void do_expand(float* __restrict__ out, int eb, int chunk) {
    // thread t in [0, 1,048,576): g = cell-group (4 cells), cb = channel base (0..15)
    const int t = chunk * 256 + threadIdx.x;
    const int g = t & 65535;
    const int cb = t >> 16;
    const int cell = g << 2;

    const unsigned char* fl = g_flag + eb * HW;
    const float* ab = g_acc + (size_t)eb * HW * CCH;
    float4* dst = (float4*)(out + (size_t)eb * CCH * HW);

    const uchar4 f4 = *(const uchar4*)(fl + cell);
    const bool any = (f4.x | f4.y | f4.z | f4.w) != 0;

    #pragma unroll
    for (int k = 0; k < 4; k++) {
        const int c = cb + 16 * k;
        float4 val = make_float4(0.f, 0.f, 0.f, 0.f);
        if (any) {
            if (f4.x) val.x = ab[(size_t)(cell + 0) * CCH + c];
            if (f4.y) val.y = ab[(size_t)(cell + 1) * CCH + c];
            if (f4.z) val.z = ab[(size_t)(cell + 2) * CCH + c];
            if (f4.w) val.w = ab[(size_t)(cell + 3) * CCH + c];
        }
        dst[c * (HW / 4) + g] = val;         // coalesced: consecutive t -> consecutive g
    }
}

// ---------------- pipeline stage (striped when both phases active) ----------------
__global__ __launch_bounds__(256) void stage_kernel(
    const float* __restrict__ pillars, const int* __restrict__ coords,
    const float* __restrict__ w, const float* __restrict__ bias,
    float* __restrict__ out, int pfn_batch, int exp_batch)
{
    const int bid = blockIdx.x;
    if (pfn_batch >= 0 && exp_batch >= 0) {
        // striped grid of 6000: pfn at bid&3==3 (1500), expand elsewhere (4500 slots)
        if ((bid & 3) == 3) {
            do_pfn(pillars, coords, w, bias, pfn_batch, bid >> 2);
        } else {
            const int eid = bid - (bid >> 2);   // contiguous [0, 4500)
            if (eid < NEXP) do_expand(out, exp_batch, eid);
        }
    } else if (pfn_batch >= 0) {
        do_pfn(pillars, coords, w, bias, pfn_batch, bid);
    } else {
        do_expand(out, exp_batch, bid);
    }
}

extern "C" void kernel_launch(void* const* d_in, const int* in_sizes, int n_in,
                              void* d_out, int out_size) {
    const float* pillars = (const float*)d_in[0];
    const int*   coords  = (const int*)d_in[1];
    const float* pfn_w   = (const float*)d_in[2];
    const float* pfn_b   = (const float*)d_in[3];
    float* out = (float*)d_out;

    prep_kernel<<<256 + 4 * NPILLARS / PPB, 256>>>(coords);
    stage_kernel<<<NPFN, 256>>>(pillars, coords, pfn_w, pfn_b, out, 0, -1);
    stage_kernel<<<STRIPED_GRID, 256>>>(pillars, coords, pfn_w, pfn_b, out, 1, 0);
    stage_kernel<<<STRIPED_GRID, 256>>>(pillars, coords, pfn_w, pfn_b, out, 2, 1);
    stage_kernel<<<STRIPED_GRID, 256>>>(pillars, coords, pfn_w, pfn_b, out, 3, 2);
    stage_kernel<<<NEXP, 256>>>(pillars, coords, pfn_w, pfn_b, out, -1, 3);
}